// round 14
// baseline (speedup 1.0000x reference)
#include <cuda_runtime.h>
#include <cuda_fp16.h>
#include <cstdint>

#define DIM 1024
#define M_TOTAL 8192
#define N_TOTAL 3072
#define RANK 16

// ---------------- scratch (module-static device arrays; no runtime alloc) ----
__device__ __half g_X16[(size_t)M_TOTAL * DIM];   // 16 MB fp16 activations
__device__ __half g_W16[(size_t)N_TOTAL * DIM];   // 6 MB fp16 merged weights

// ---------------- PTX helpers (baseline ISA only: sm_80-era) ------------------
__device__ __forceinline__ uint32_t smem_u32(const void* p) {
    uint32_t a;
    asm("{ .reg .u64 t; cvta.to.shared.u64 t, %1; cvt.u32.u64 %0, t; }" : "=r"(a) : "l"(p));
    return a;
}

#define CP_ASYNC16(dst_smem, src_g) \
    asm volatile("cp.async.cg.shared.global [%0], [%1], 16;" :: "r"(dst_smem), "l"(src_g) : "memory")
#define CP_ASYNC_COMMIT() asm volatile("cp.async.commit_group;" ::: "memory")
#define CP_ASYNC_WAIT(n)  asm volatile("cp.async.wait_group %0;" :: "n"(n) : "memory")

__device__ __forceinline__ void ldmatrix_x4(uint32_t* r, uint32_t addr) {
    asm("ldmatrix.sync.aligned.m8n8.x4.shared.b16 {%0,%1,%2,%3}, [%4];"
        : "=r"(r[0]), "=r"(r[1]), "=r"(r[2]), "=r"(r[3]) : "r"(addr) : "memory");
}

__device__ __forceinline__ void mma16816(float* c, const uint32_t* a,
                                         uint32_t b0, uint32_t b1) {
    asm("mma.sync.aligned.m16n8k16.row.col.f32.f16.f16.f32 "
        "{%0,%1,%2,%3}, {%4,%5,%6,%7}, {%8,%9}, {%0,%1,%2,%3};"
        : "+f"(c[0]), "+f"(c[1]), "+f"(c[2]), "+f"(c[3])
        : "r"(a[0]), "r"(a[1]), "r"(a[2]), "r"(a[3]), "r"(b0), "r"(b1));
}

// evict-first fp32 loads for one-time streams (keep L2 for X16/W16)
__device__ __forceinline__ float4 ldcs4(const float* p) {
    float4 v;
    asm("ld.global.cs.v4.f32 {%0,%1,%2,%3}, [%4];"
        : "=f"(v.x), "=f"(v.y), "=f"(v.z), "=f"(v.w) : "l"(p));
    return v;
}

// ---------------- fused prep kernel -------------------------------------------
#define WPREP_BLOCKS ((N_TOTAL / 128) * (DIM / 64))   // 384
#define CONVERT_BLOCKS ((M_TOTAL * DIM) / (256 * 16)) // 2048

__global__ void __launch_bounds__(256)
prep_kernel(const float* __restrict__ x, const float* __restrict__ W,
            const float* __restrict__ Aq, const float* __restrict__ Bq,
            const float* __restrict__ Ak, const float* __restrict__ Bk,
            const float* __restrict__ Av, const float* __restrict__ Bv,
            const float* __restrict__ alpha_p) {
    int tid = threadIdx.x;
    if (blockIdx.x >= WPREP_BLOCKS) {
        size_t i = ((size_t)(blockIdx.x - WPREP_BLOCKS) * 256 + tid) * 16;
        float4 a0 = ldcs4(x + i);
        float4 a1 = ldcs4(x + i + 4);
        float4 a2 = ldcs4(x + i + 8);
        float4 a3 = ldcs4(x + i + 12);
        __half2 h[8];
        h[0] = __floats2half2_rn(a0.x, a0.y);
        h[1] = __floats2half2_rn(a0.z, a0.w);
        h[2] = __floats2half2_rn(a1.x, a1.y);
        h[3] = __floats2half2_rn(a1.z, a1.w);
        h[4] = __floats2half2_rn(a2.x, a2.y);
        h[5] = __floats2half2_rn(a2.z, a2.w);
        h[6] = __floats2half2_rn(a3.x, a3.y);
        h[7] = __floats2half2_rn(a3.z, a3.w);
        *reinterpret_cast<uint4*>(g_X16 + i)     = *reinterpret_cast<uint4*>(h);
        *reinterpret_cast<uint4*>(g_X16 + i + 8) = *reinterpret_cast<uint4*>(h + 4);
        return;
    }
    __shared__ float sA[RANK][64];
    __shared__ float sB[128][RANK];
    int idx = blockIdx.x;
    int n0 = (idx % (N_TOTAL / 128)) * 128;
    int k0 = (idx / (N_TOTAL / 128)) * 64;
    int seg = n0 >> 10;
    int nl0 = n0 & 1023;
    const float* A = (seg == 0) ? Aq : (seg == 1) ? Ak : Av;
    const float* B = (seg == 0) ? Bq : (seg == 1) ? Bk : Bv;
    for (int i = tid; i < RANK * 64; i += 256)
        sA[i >> 6][i & 63] = A[(size_t)(i >> 6) * DIM + k0 + (i & 63)];
    for (int i = tid; i < 128 * RANK; i += 256)
        sB[i >> 4][i & 15] = B[(size_t)(nl0 + (i >> 4)) * RANK + (i & 15)];
    __syncthreads();
    float al = *alpha_p;
    for (int e = tid; e < 128 * 64; e += 256) {
        int d = e >> 6, c = e & 63;
        float acc = 0.f;
#pragma unroll
        for (int r = 0; r < RANK; r++) acc += sB[d][r] * sA[r][c];
        size_t gi = (size_t)(n0 + d) * DIM + k0 + c;
        float wv;
        asm("ld.global.cs.f32 %0, [%1];" : "=f"(wv) : "l"(W + gi));
        g_W16[gi] = __float2half_rn(wv + al * acc);
    }
}

// ---------------- GEMM: HMMA (mma.sync) + bias epilogue -----------------------
// out[M,N] = X16[M,K] @ W16[N,K]^T + bias ;  M=8192 N=3072 K=1024
// CTA tile 128x96, 128 threads (2x2 warps), warp tile 64x48, occupancy 3,
// non-persistent grid 2048, per-CTA ks rotation (R13), .cs epilogue stores.
// R14: ko[4] address table + per-stage bases (1 IADD3 per LDSM address) and
// dependency-ordered LDSM issue (af0,bf0,bf1,bf2,af1,af2,af3) so the lead
// MMAs' operands are the earliest-issued loads.
#define BM 128
#define BN 96
#define BK 64
#define KCHUNKS (DIM / BK)                 // 16
#define STAGE_BYTES (BM * 128 + BN * 128)  // 28672
#define GEMM_SMEM (2 * STAGE_BYTES)        // 57344

__global__ void __launch_bounds__(128, 3)
gemm_kernel(const float* __restrict__ bias, float* __restrict__ out) {
    extern __shared__ char smem[];
    uint32_t sb = smem_u32(smem);
    const int tid = threadIdx.x, wid = tid >> 5, lane = tid & 31;
    const int m0 = blockIdx.y * BM, n0 = blockIdx.x * BN;
    const int wm = wid >> 1;   // 0..1 -> 64 rows each
    const int wn = wid & 1;    // 0..1 -> 48 cols each
    const uint32_t ksrot = blockIdx.x & 3;

    const char* gA = (const char*)(g_X16 + (size_t)m0 * DIM);
    const char* gB = (const char*)(g_W16 + (size_t)n0 * DIM);

    // cp.async: per-thread base; item i = base + i*2048 (smem) / +i*32768 (glob)
    const int cr = tid >> 3, cc = tid & 7;
    const uint32_t g0  = (uint32_t)(cr * (DIM * 2) + cc * 16);
    const uint32_t sw0 = (uint32_t)(cr * 128 + ((cc ^ (cr & 7)) << 4));

    // ldmatrix bases; ko[] table is kc-invariant (rotation folded in)
    const int lrow = (lane & 7) + ((lane >> 3) & 1) * 8;
    const int lch = lane >> 4;
    const int s7 = lrow & 7;
    const uint32_t swX = (uint32_t)((s7 & 6) << 4);
    const uint32_t swL = (uint32_t)((lch ^ (s7 & 1)) << 4);
    uint32_t ko[4];
#pragma unroll
    for (int ks = 0; ks < 4; ks++)
        ko[ks] = ((((uint32_t)ks + ksrot) & 3) << 5) ^ swX;

    // per-stage fragment row bases (stage bit folded once, not per kc)
    const uint32_t aB0 = (uint32_t)((wm * 64 + lrow) * 128) + swL;
    const uint32_t bB0 = (uint32_t)((BM + wn * 48 + lrow) * 128) + swL;
    const uint32_t arbS[2] = { sb + aB0, sb + STAGE_BYTES + aB0 };
    const uint32_t brbS[2] = { sb + bB0, sb + STAGE_BYTES + bB0 };

    float c[4][6][4];
#pragma unroll
    for (int i = 0; i < 4; i++)
#pragma unroll
        for (int j = 0; j < 6; j++)
#pragma unroll
            for (int k = 0; k < 4; k++) c[i][j][k] = 0.f;

    // ---- prologue: chunk 0 -> stage 0 ----
    {
        uint32_t sa = sb;
        uint32_t sbb = sa + BM * 128;
#pragma unroll
        for (int i = 0; i < 8; i++) CP_ASYNC16(sa + sw0 + i * 2048, gA + g0 + (size_t)i * 32768);
#pragma unroll
        for (int i = 0; i < 6; i++) CP_ASYNC16(sbb + sw0 + i * 2048, gB + g0 + (size_t)i * 32768);
        CP_ASYNC_COMMIT();
    }

    for (int kc = 0; kc < KCHUNKS; kc++) {
        CP_ASYNC_WAIT(0);
        __syncthreads();

        if (kc + 1 < KCHUNKS) {
            uint32_t sa = sb + ((kc + 1) & 1) * STAGE_BYTES;
            uint32_t sbb = sa + BM * 128;
            const char* a = gA + (kc + 1) * (BK * 2);
            const char* b = gB + (kc + 1) * (BK * 2);
#pragma unroll
            for (int i = 0; i < 8; i++) CP_ASYNC16(sa + sw0 + i * 2048, a + g0 + (size_t)i * 32768);
#pragma unroll
            for (int i = 0; i < 6; i++) CP_ASYNC16(sbb + sw0 + i * 2048, b + g0 + (size_t)i * 32768);
            CP_ASYNC_COMMIT();
        }

        const uint32_t arb = arbS[kc & 1];
        const uint32_t brb = brbS[kc & 1];

#pragma unroll
        for (int ks = 0; ks < 4; ks++) {
            const uint32_t k4 = ko[ks];
            uint32_t af[4][4], bf[3][4];
            // dependency-ordered issue: lead MMA (af0,bf0) deps go first
            ldmatrix_x4(af[0], arb + 0 * 2048 + k4);
            ldmatrix_x4(bf[0], brb + 0 * 2048 + k4);
            ldmatrix_x4(bf[1], brb + 1 * 2048 + k4);
            ldmatrix_x4(bf[2], brb + 2 * 2048 + k4);
            ldmatrix_x4(af[1], arb + 1 * 2048 + k4);
            ldmatrix_x4(af[2], arb + 2 * 2048 + k4);
            ldmatrix_x4(af[3], arb + 3 * 2048 + k4);
#pragma unroll
            for (int mt = 0; mt < 4; mt++)
#pragma unroll
                for (int n8 = 0; n8 < 6; n8++) {
                    int nt = n8 >> 1, hi = n8 & 1;
                    mma16816(c[mt][n8], af[mt], bf[nt][hi], bf[nt][2 + hi]);
                }
        }
    }

    // ------- epilogue: +bias, .cs float2 stores (evict-first) -------
#pragma unroll
    for (int n8 = 0; n8 < 6; n8++) {
        int n = n0 + wn * 48 + n8 * 8 + ((lane & 3) << 1);
        float bv0 = bias[n], bv1 = bias[n + 1];
#pragma unroll
        for (int mt = 0; mt < 4; mt++) {
            int m = m0 + wm * 64 + mt * 16 + (lane >> 2);
            float2 v0 = make_float2(c[mt][n8][0] + bv0, c[mt][n8][1] + bv1);
            float2 v1 = make_float2(c[mt][n8][2] + bv0, c[mt][n8][3] + bv1);
            __stcs(reinterpret_cast<float2*>(out + (size_t)m * N_TOTAL + n), v0);
            __stcs(reinterpret_cast<float2*>(out + (size_t)(m + 8) * N_TOTAL + n), v1);
        }
    }
}

// ---------------- launch -------------------------------------------------------
extern "C" void kernel_launch(void* const* d_in, const int* in_sizes, int n_in,
                              void* d_out, int out_size) {
    const float* x     = (const float*)d_in[0];
    const float* W_qkv = (const float*)d_in[1];
    const float* b_qkv = (const float*)d_in[2];
    const float* A_q   = (const float*)d_in[3];
    const float* B_q   = (const float*)d_in[4];
    const float* A_k   = (const float*)d_in[5];
    const float* B_k   = (const float*)d_in[6];
    const float* A_v   = (const float*)d_in[7];
    const float* B_v   = (const float*)d_in[8];
    const float* alpha = (const float*)d_in[9];
    float* out = (float*)d_out;

    static bool attr_done = false;
    if (!attr_done) {
        cudaFuncSetAttribute(gemm_kernel, cudaFuncAttributeMaxDynamicSharedMemorySize, GEMM_SMEM);
        attr_done = true;
    }

    prep_kernel<<<WPREP_BLOCKS + CONVERT_BLOCKS, 256>>>(
        x, W_qkv, A_q, B_q, A_k, B_k, A_v, B_v, alpha);
    gemm_kernel<<<dim3(N_TOTAL / BN, M_TOTAL / BM), 128, GEMM_SMEM>>>(b_qkv, out);
}

// round 15
// speedup vs baseline: 1.0518x; 1.0518x over previous
#include <cuda_runtime.h>
#include <cuda_fp16.h>
#include <cstdint>

#define DIM 1024
#define M_TOTAL 8192
#define N_TOTAL 3072
#define RANK 16

// ---------------- scratch (module-static device arrays; no runtime alloc) ----
__device__ __half g_X16[(size_t)M_TOTAL * DIM];   // 16 MB fp16 activations
__device__ __half g_W16[(size_t)N_TOTAL * DIM];   // 6 MB fp16 merged weights

// ---------------- PTX helpers (baseline ISA only: sm_80-era) ------------------
__device__ __forceinline__ uint32_t smem_u32(const void* p) {
    uint32_t a;
    asm("{ .reg .u64 t; cvta.to.shared.u64 t, %1; cvt.u32.u64 %0, t; }" : "=r"(a) : "l"(p));
    return a;
}

#define CP_ASYNC16(dst_smem, src_g) \
    asm volatile("cp.async.cg.shared.global [%0], [%1], 16;" :: "r"(dst_smem), "l"(src_g) : "memory")
#define CP_ASYNC_COMMIT() asm volatile("cp.async.commit_group;" ::: "memory")
#define CP_ASYNC_WAIT(n)  asm volatile("cp.async.wait_group %0;" :: "n"(n) : "memory")

__device__ __forceinline__ void ldmatrix_x4(uint32_t* r, uint32_t addr) {
    asm("ldmatrix.sync.aligned.m8n8.x4.shared.b16 {%0,%1,%2,%3}, [%4];"
        : "=r"(r[0]), "=r"(r[1]), "=r"(r[2]), "=r"(r[3]) : "r"(addr) : "memory");
}

__device__ __forceinline__ void mma16816(float* c, const uint32_t* a,
                                         uint32_t b0, uint32_t b1) {
    asm("mma.sync.aligned.m16n8k16.row.col.f32.f16.f16.f32 "
        "{%0,%1,%2,%3}, {%4,%5,%6,%7}, {%8,%9}, {%0,%1,%2,%3};"
        : "+f"(c[0]), "+f"(c[1]), "+f"(c[2]), "+f"(c[3])
        : "r"(a[0]), "r"(a[1]), "r"(a[2]), "r"(a[3]), "r"(b0), "r"(b1));
}

// ---------------- fused prep kernel (verbatim R13) -----------------------------
#define WPREP_BLOCKS ((N_TOTAL / 128) * (DIM / 64))   // 384
#define CONVERT_BLOCKS ((M_TOTAL * DIM) / (256 * 16)) // 2048

__global__ void __launch_bounds__(256)
prep_kernel(const float* __restrict__ x, const float* __restrict__ W,
            const float* __restrict__ Aq, const float* __restrict__ Bq,
            const float* __restrict__ Ak, const float* __restrict__ Bk,
            const float* __restrict__ Av, const float* __restrict__ Bv,
            const float* __restrict__ alpha_p) {
    int tid = threadIdx.x;
    if (blockIdx.x >= WPREP_BLOCKS) {
        size_t i = ((size_t)(blockIdx.x - WPREP_BLOCKS) * 256 + tid) * 16;
        float4 a0 = *reinterpret_cast<const float4*>(x + i);
        float4 a1 = *reinterpret_cast<const float4*>(x + i + 4);
        float4 a2 = *reinterpret_cast<const float4*>(x + i + 8);
        float4 a3 = *reinterpret_cast<const float4*>(x + i + 12);
        __half2 h[8];
        h[0] = __floats2half2_rn(a0.x, a0.y);
        h[1] = __floats2half2_rn(a0.z, a0.w);
        h[2] = __floats2half2_rn(a1.x, a1.y);
        h[3] = __floats2half2_rn(a1.z, a1.w);
        h[4] = __floats2half2_rn(a2.x, a2.y);
        h[5] = __floats2half2_rn(a2.z, a2.w);
        h[6] = __floats2half2_rn(a3.x, a3.y);
        h[7] = __floats2half2_rn(a3.z, a3.w);
        *reinterpret_cast<uint4*>(g_X16 + i)     = *reinterpret_cast<uint4*>(h);
        *reinterpret_cast<uint4*>(g_X16 + i + 8) = *reinterpret_cast<uint4*>(h + 4);
        return;
    }
    __shared__ float sA[RANK][64];
    __shared__ float sB[128][RANK];
    int idx = blockIdx.x;
    int n0 = (idx % (N_TOTAL / 128)) * 128;
    int k0 = (idx / (N_TOTAL / 128)) * 64;
    int seg = n0 >> 10;
    int nl0 = n0 & 1023;
    const float* A = (seg == 0) ? Aq : (seg == 1) ? Ak : Av;
    const float* B = (seg == 0) ? Bq : (seg == 1) ? Bk : Bv;
    for (int i = tid; i < RANK * 64; i += 256)
        sA[i >> 6][i & 63] = A[(size_t)(i >> 6) * DIM + k0 + (i & 63)];
    for (int i = tid; i < 128 * RANK; i += 256)
        sB[i >> 4][i & 15] = B[(size_t)(nl0 + (i >> 4)) * RANK + (i & 15)];
    __syncthreads();
    float al = *alpha_p;
    for (int e = tid; e < 128 * 64; e += 256) {
        int d = e >> 6, c = e & 63;
        float acc = 0.f;
#pragma unroll
        for (int r = 0; r < RANK; r++) acc += sB[d][r] * sA[r][c];
        size_t gi = (size_t)(n0 + d) * DIM + k0 + c;
        g_W16[gi] = __float2half_rn(W[gi] + al * acc);
    }
}

// ---------------- GEMM: HMMA (mma.sync) + bias epilogue -----------------------
// R13 chassis (CTA 128x96, 128 thr, warp 64x48, occ 3, 2-stage, ks-rotation,
// .cs epilogue). R15 single change: dependency-ordered LDSM issue — the lead
// MMA's operands (af0, bf0) are the FIRST loads issued each ks step.
#define BM 128
#define BN 96
#define BK 64
#define KCHUNKS (DIM / BK)                 // 16
#define STAGE_BYTES (BM * 128 + BN * 128)  // 28672
#define GEMM_SMEM (2 * STAGE_BYTES)        // 57344

__global__ void __launch_bounds__(128, 3)
gemm_kernel(const float* __restrict__ bias, float* __restrict__ out) {
    extern __shared__ char smem[];
    uint32_t sb = smem_u32(smem);
    const int tid = threadIdx.x, wid = tid >> 5, lane = tid & 31;
    const int m0 = blockIdx.y * BM, n0 = blockIdx.x * BN;
    const int wm = wid >> 1;   // 0..1 -> 64 rows each
    const int wn = wid & 1;    // 0..1 -> 48 cols each
    const uint32_t ksrot = blockIdx.x & 3;   // per-CTA phase offset (k-substeps commute)

    const char* gA = (const char*)(g_X16 + (size_t)m0 * DIM);
    const char* gB = (const char*)(g_W16 + (size_t)n0 * DIM);

    // cp.async: per-thread base; item i = base + i*2048 (smem) / +i*32768 (glob)
    const int cr = tid >> 3, cc = tid & 7;
    const uint32_t g0  = (uint32_t)(cr * (DIM * 2) + cc * 16);
    const uint32_t sw0 = (uint32_t)(cr * 128 + ((cc ^ (cr & 7)) << 4));

    // ldmatrix: row-group parity s = lrow&7 is tile-invariant -> 2 XOR regs.
    const int lrow = (lane & 7) + ((lane >> 3) & 1) * 8;
    const int lch = lane >> 4;
    const int s7 = lrow & 7;
    const uint32_t swX = (uint32_t)((s7 & 6) << 4);          // XORed with ks<<5
    const uint32_t swL = (uint32_t)((lch ^ (s7 & 1)) << 4);  // constant part
    const uint32_t aB0 = (uint32_t)((wm * 64 + lrow) * 128) + swL;
    const uint32_t bB0 = (uint32_t)((BM + wn * 48 + lrow) * 128) + swL;

    float c[4][6][4];
#pragma unroll
    for (int i = 0; i < 4; i++)
#pragma unroll
        for (int j = 0; j < 6; j++)
#pragma unroll
            for (int k = 0; k < 4; k++) c[i][j][k] = 0.f;

    // ---- prologue: chunk 0 -> stage 0 ----
    {
        uint32_t sa = sb;
        uint32_t sbb = sa + BM * 128;
#pragma unroll
        for (int i = 0; i < 8; i++) CP_ASYNC16(sa + sw0 + i * 2048, gA + g0 + (size_t)i * 32768);
#pragma unroll
        for (int i = 0; i < 6; i++) CP_ASYNC16(sbb + sw0 + i * 2048, gB + g0 + (size_t)i * 32768);
        CP_ASYNC_COMMIT();
    }

    for (int kc = 0; kc < KCHUNKS; kc++) {
        CP_ASYNC_WAIT(0);
        __syncthreads();

        if (kc + 1 < KCHUNKS) {            // prefetch kc+1 into the other stage
            uint32_t sa = sb + ((kc + 1) & 1) * STAGE_BYTES;
            uint32_t sbb = sa + BM * 128;
            const char* a = gA + (kc + 1) * (BK * 2);
            const char* b = gB + (kc + 1) * (BK * 2);
#pragma unroll
            for (int i = 0; i < 8; i++) CP_ASYNC16(sa + sw0 + i * 2048, a + g0 + (size_t)i * 32768);
#pragma unroll
            for (int i = 0; i < 6; i++) CP_ASYNC16(sbb + sw0 + i * 2048, b + g0 + (size_t)i * 32768);
            CP_ASYNC_COMMIT();
        }

        const uint32_t stg = sb + (kc & 1) * STAGE_BYTES;
        const uint32_t arb = stg + aB0;
        const uint32_t brb = stg + bB0;

#pragma unroll
        for (int ks = 0; ks < 4; ks++) {
            const uint32_t kse = (ks + ksrot) & 3;       // rotated k-substep
            const uint32_t ko = (kse << 5) ^ swX;
            uint32_t af[4][4], bf[3][4];
            // R15: dependency-ordered issue — lead MMA's operands first
            ldmatrix_x4(af[0], arb + 0 * 2048 + ko);
            ldmatrix_x4(bf[0], brb + 0 * 2048 + ko);
            ldmatrix_x4(bf[1], brb + 1 * 2048 + ko);
            ldmatrix_x4(bf[2], brb + 2 * 2048 + ko);
            ldmatrix_x4(af[1], arb + 1 * 2048 + ko);
            ldmatrix_x4(af[2], arb + 2 * 2048 + ko);
            ldmatrix_x4(af[3], arb + 3 * 2048 + ko);
#pragma unroll
            for (int mt = 0; mt < 4; mt++)
#pragma unroll
                for (int n8 = 0; n8 < 6; n8++) {
                    int nt = n8 >> 1, hi = n8 & 1;
                    mma16816(c[mt][n8], af[mt], bf[nt][hi], bf[nt][2 + hi]);
                }
        }
    }

    // ------- epilogue: +bias, .cs float2 stores (evict-first) -------
#pragma unroll
    for (int n8 = 0; n8 < 6; n8++) {
        int n = n0 + wn * 48 + n8 * 8 + ((lane & 3) << 1);
        float bv0 = bias[n], bv1 = bias[n + 1];
#pragma unroll
        for (int mt = 0; mt < 4; mt++) {
            int m = m0 + wm * 64 + mt * 16 + (lane >> 2);
            float2 v0 = make_float2(c[mt][n8][0] + bv0, c[mt][n8][1] + bv1);
            float2 v1 = make_float2(c[mt][n8][2] + bv0, c[mt][n8][3] + bv1);
            __stcs(reinterpret_cast<float2*>(out + (size_t)m * N_TOTAL + n), v0);
            __stcs(reinterpret_cast<float2*>(out + (size_t)(m + 8) * N_TOTAL + n), v1);
        }
    }
}

// ---------------- launch -------------------------------------------------------
extern "C" void kernel_launch(void* const* d_in, const int* in_sizes, int n_in,
                              void* d_out, int out_size) {
    const float* x     = (const float*)d_in[0];
    const float* W_qkv = (const float*)d_in[1];
    const float* b_qkv = (const float*)d_in[2];
    const float* A_q   = (const float*)d_in[3];
    const float* B_q   = (const float*)d_in[4];
    const float* A_k   = (const float*)d_in[5];
    const float* B_k   = (const float*)d_in[6];
    const float* A_v   = (const float*)d_in[7];
    const float* B_v   = (const float*)d_in[8];
    const float* alpha = (const float*)d_in[9];
    float* out = (float*)d_out;

    static bool attr_done = false;
    if (!attr_done) {
        cudaFuncSetAttribute(gemm_kernel, cudaFuncAttributeMaxDynamicSharedMemorySize, GEMM_SMEM);
        attr_done = true;
    }

    prep_kernel<<<WPREP_BLOCKS + CONVERT_BLOCKS, 256>>>(
        x, W_qkv, A_q, B_q, A_k, B_k, A_v, B_v, alpha);
    gemm_kernel<<<dim3(N_TOTAL / BN, M_TOTAL / BM), 128, GEMM_SMEM>>>(b_qkv, out);
}